// round 1
// baseline (speedup 1.0000x reference)
#include <cuda_runtime.h>

#define NN   50000
#define NE   800000
#define DIN  96
#define DH   128
#define DOUT 16

// ---------------- scratch (no allocations allowed) ----------------
__device__ float g_agg1[NN * DIN];           // 19.2 MB  sum of x[src] at dst
__device__ float g_deg [NN];                 // in-degree (float)
__device__ float g_h   [NN * DH];            // 25.6 MB  layer-1 output
__device__ float g_r   [NN * 32];            // [p | q] = h @ [W2_l | W2_r]
__device__ float g_agg2[NN * DOUT];          // sum of p[src] at dst
__device__ int   g_is64;

// ---------------- dtype detection for edge_index ----------------
// int64 little-endian with ids < 2^31 => every odd int32 word is 0.
__global__ void k_detect(const int* __restrict__ ei) {
    int all0 = 1;
#pragma unroll 1
    for (int i = 1; i < 256; i += 2) all0 &= (ei[i] == 0);
    g_is64 = all0;
}

// ---------------- layer-1 edge aggregation + degree ----------------
// one thread per (edge, float4-chunk); 24 chunks cover 96 dims
__global__ void k_agg_x(const int* __restrict__ ei32,
                        const long long* __restrict__ ei64,
                        const float* __restrict__ x) {
    int gid = blockIdx.x * blockDim.x + threadIdx.x;
    if (gid >= NE * 24) return;
    int e = gid / 24;
    int c = gid - e * 24;
    int src, dst;
    if (g_is64) { src = (int)ei64[e]; dst = (int)ei64[NE + e]; }
    else        { src = ei32[e];      dst = ei32[NE + e]; }

    const float4 v = ((const float4*)(x + (size_t)src * DIN))[c];
    float4* o = ((float4*)(g_agg1 + (size_t)dst * DIN)) + c;
    asm volatile("red.global.add.v4.f32 [%0], {%1,%2,%3,%4};"
                 :: "l"(o), "f"(v.x), "f"(v.y), "f"(v.z), "f"(v.w) : "memory");
    if (c == 0) atomicAdd(&g_deg[dst], 1.0f);
}

// ---------------- layer 1: h = relu((agg1/deg) @ W1_l + b1 + x @ W1_r) ----------------
// block = 128 threads (one output column each), 8 rows per block
__global__ void k_gemm1(const float* __restrict__ x,
                        const float* __restrict__ W1l,
                        const float* __restrict__ b1,
                        const float* __restrict__ W1r) {
    __shared__ float xs[8][DIN];
    __shared__ float as[8][DIN];
    __shared__ float inv[8];

    const int row0 = blockIdx.x * 8;
    const int tid  = threadIdx.x;

    if (tid < 8) {
        int g = row0 + tid;
        float d = (g < NN) ? g_deg[g] : 1.0f;
        inv[tid] = 1.0f / fmaxf(d, 1.0f);
    }
    __syncthreads();

    for (int idx = tid; idx < 8 * DIN; idx += 128) {
        int r = idx / DIN, k = idx - r * DIN;
        int g = row0 + r;
        float xv = 0.f, av = 0.f;
        if (g < NN) {
            xv = x[(size_t)g * DIN + k];
            av = g_agg1[(size_t)g * DIN + k] * inv[r];
        }
        xs[r][k] = xv;
        as[r][k] = av;
    }
    __syncthreads();

    const int j = tid;            // output column 0..127
    float acc[8];
    const float bj = b1[j];
#pragma unroll
    for (int r = 0; r < 8; r++) acc[r] = bj;

#pragma unroll 4
    for (int k = 0; k < DIN; k++) {
        float wl = W1l[k * DH + j];
        float wr = W1r[k * DH + j];
#pragma unroll
        for (int r = 0; r < 8; r++)
            acc[r] += as[r][k] * wl + xs[r][k] * wr;
    }

#pragma unroll
    for (int r = 0; r < 8; r++) {
        int g = row0 + r;
        if (g < NN) g_h[(size_t)g * DH + j] = fmaxf(acc[r], 0.0f);
    }
}

// ---------------- layer-2 projections: r = h @ [W2_l | W2_r]  (128 x 32) ----------------
// block = 256 threads: (8 rows) x (32 cols)
__global__ void k_gemm2(const float* __restrict__ W2l,
                        const float* __restrict__ W2r) {
    __shared__ float w[DH * 32];          // w[k*32 + j]: j<16 -> W2_l, j>=16 -> W2_r
    __shared__ float hs[8][DH];

    const int tid = threadIdx.x;
    for (int i = tid; i < DH * DOUT; i += 256) {
        int k = i / DOUT, j = i - k * DOUT;
        w[k * 32 + j]        = W2l[i];
        w[k * 32 + 16 + j]   = W2r[i];
    }
    const int row0 = blockIdx.x * 8;
    for (int i = tid; i < 8 * DH; i += 256) {
        int r = i / DH, k = i - r * DH;
        int g = row0 + r;
        hs[r][k] = (g < NN) ? g_h[(size_t)g * DH + k] : 0.0f;
    }
    __syncthreads();

    const int j = tid & 31;
    const int r = tid >> 5;
    float acc = 0.f;
#pragma unroll 8
    for (int k = 0; k < DH; k++)
        acc += hs[r][k] * w[k * 32 + j];

    int g = row0 + r;
    if (g < NN) g_r[(size_t)g * 32 + j] = acc;
}

// ---------------- layer-2 edge aggregation of projected messages (16 dims) ----------------
__global__ void k_agg_p(const int* __restrict__ ei32,
                        const long long* __restrict__ ei64) {
    int gid = blockIdx.x * blockDim.x + threadIdx.x;
    if (gid >= NE * 4) return;
    int e = gid >> 2;
    int c = gid & 3;
    int src, dst;
    if (g_is64) { src = (int)ei64[e]; dst = (int)ei64[NE + e]; }
    else        { src = ei32[e];      dst = ei32[NE + e]; }

    const float4 v = ((const float4*)(g_r + (size_t)src * 32))[c];   // p = first 16
    float4* o = ((float4*)(g_agg2 + (size_t)dst * DOUT)) + c;
    asm volatile("red.global.add.v4.f32 [%0], {%1,%2,%3,%4};"
                 :: "l"(o), "f"(v.x), "f"(v.y), "f"(v.z), "f"(v.w) : "memory");
}

// ---------------- epilogue: softmax(agg2/deg + b2 + q) ----------------
__global__ void k_finalize(const float* __restrict__ b2,
                           float* __restrict__ out) {
    int row = blockIdx.x * blockDim.x + threadIdx.x;
    if (row >= NN) return;
    float inv = 1.0f / fmaxf(g_deg[row], 1.0f);

    float v[DOUT];
    float mx = -1e30f;
#pragma unroll
    for (int j = 0; j < DOUT; j++) {
        v[j] = g_agg2[(size_t)row * DOUT + j] * inv + b2[j]
             + g_r[(size_t)row * 32 + 16 + j];
        mx = fmaxf(mx, v[j]);
    }
    float s = 0.f;
#pragma unroll
    for (int j = 0; j < DOUT; j++) {
        v[j] = __expf(v[j] - mx);
        s += v[j];
    }
    float is = 1.0f / s;
#pragma unroll
    for (int j = 0; j < DOUT; j++)
        out[(size_t)row * DOUT + j] = v[j] * is;
}

// ---------------- launch ----------------
extern "C" void kernel_launch(void* const* d_in, const int* in_sizes, int n_in,
                              void* d_out, int out_size) {
    const float*     x    = (const float*)d_in[0];
    const int*       ei32 = (const int*)d_in[1];
    const long long* ei64 = (const long long*)d_in[1];
    const float*     W1l  = (const float*)d_in[2];
    const float*     b1   = (const float*)d_in[3];
    const float*     W1r  = (const float*)d_in[4];
    const float*     W2l  = (const float*)d_in[5];
    const float*     b2   = (const float*)d_in[6];
    const float*     W2r  = (const float*)d_in[7];
    float* out = (float*)d_out;

    void *agg1p, *degp, *agg2p;
    cudaGetSymbolAddress(&agg1p, g_agg1);
    cudaGetSymbolAddress(&degp,  g_deg);
    cudaGetSymbolAddress(&agg2p, g_agg2);
    cudaMemsetAsync(agg1p, 0, sizeof(float) * NN * DIN, 0);
    cudaMemsetAsync(degp,  0, sizeof(float) * NN, 0);
    cudaMemsetAsync(agg2p, 0, sizeof(float) * NN * DOUT, 0);

    k_detect<<<1, 1>>>(ei32);
    k_agg_x<<<(NE * 24 + 255) / 256, 256>>>(ei32, ei64, x);
    k_gemm1<<<NN / 8, 128>>>(x, W1l, b1, W1r);
    k_gemm2<<<NN / 8, 256>>>(W2l, W2r);
    k_agg_p<<<(NE * 4 + 255) / 256, 256>>>(ei32, ei64);
    k_finalize<<<(NN + 127) / 128, 128>>>(b2, out);
}

// round 2
// speedup vs baseline: 1.2036x; 1.2036x over previous
#include <cuda_runtime.h>

#define NN   50000
#define NE   800000
#define DIN  96
#define DH   128
#define DOUT 16

typedef unsigned long long ull;

// ---------------- scratch (no allocations allowed) ----------------
__device__ float g_agg1[NN * DIN];           // 19.2 MB  sum of x[src] at dst
__device__ float g_deg [NN];                 // in-degree (float)
__device__ float g_r   [NN * 32];            // [p | q] = h @ [W2_l | W2_r]
__device__ float g_agg2[NN * DOUT];          // sum of p[src] at dst
__device__ int   g_is64;

// ---------------- f32x2 packed helpers (sm_100+) ----------------
__device__ __forceinline__ ull pk(float a, float b) {
    ull r; asm("mov.b64 %0, {%1,%2};" : "=l"(r) : "f"(a), "f"(b)); return r;
}
__device__ __forceinline__ float2 upk(ull a) {
    float2 f; asm("mov.b64 {%0,%1}, %2;" : "=f"(f.x), "=f"(f.y) : "l"(a)); return f;
}
__device__ __forceinline__ ull fma2(ull a, ull b, ull c) {
    ull d; asm("fma.rn.f32x2 %0, %1, %2, %3;" : "=l"(d) : "l"(a), "l"(b), "l"(c)); return d;
}

// ---------------- dtype detection for edge_index ----------------
__global__ void k_detect(const int* __restrict__ ei) {
    int all0 = 1;
#pragma unroll 1
    for (int i = 1; i < 256; i += 2) all0 &= (ei[i] == 0);
    g_is64 = all0;
}

// ---------------- layer-1 edge aggregation + degree ----------------
__global__ void k_agg_x(const int* __restrict__ ei32,
                        const long long* __restrict__ ei64,
                        const float* __restrict__ x) {
    int gid = blockIdx.x * blockDim.x + threadIdx.x;
    if (gid >= NE * 24) return;
    int e = gid / 24;
    int c = gid - e * 24;
    int src, dst;
    if (g_is64) { src = (int)ei64[e]; dst = (int)ei64[NE + e]; }
    else        { src = ei32[e];      dst = ei32[NE + e]; }

    const float4 v = ((const float4*)(x + (size_t)src * DIN))[c];
    float4* o = ((float4*)(g_agg1 + (size_t)dst * DIN)) + c;
    asm volatile("red.global.add.v4.f32 [%0], {%1,%2,%3,%4};"
                 :: "l"(o), "f"(v.x), "f"(v.y), "f"(v.z), "f"(v.w) : "memory");
    if (c == 0) atomicAdd(&g_deg[dst], 1.0f);
}

// ---------------- fused layer-1 GEMM + layer-2 projection ----------------
// block = 128 threads, 8 rows per block (50000/8 = 6250 blocks, exact)
// stage A: h[8][128] = relu((agg1/deg)@W1_l + b1 + x@W1_r)   (f32x2 packed)
// stage B: r[8][32]  = h @ [W2_l | W2_r]                      (f32x2 packed)
__global__ void __launch_bounds__(128) k_fused(
        const float* __restrict__ x,
        const float* __restrict__ W1l,
        const float* __restrict__ b1,
        const float* __restrict__ W1r,
        const float* __restrict__ W2l,
        const float* __restrict__ W2r) {

    // asp/xsp: per k, 8 row values packed as 2x ulonglong2 (rows 0..3, 4..7)
    __shared__ ulonglong2 aspv[DIN][2];       // 3 KB
    __shared__ ulonglong2 xspv[DIN][2];       // 3 KB
    __shared__ ull        hsT [4][DH];        // 4 KB  [row-pair][k] packed h
    __shared__ float      wsT [32][132];      // 16.5 KB  [out col][k] (padded)
    __shared__ float      inv [8];

    const int tid  = threadIdx.x;
    const int row0 = blockIdx.x * 8;

    if (tid < 8) inv[tid] = 1.0f / fmaxf(g_deg[row0 + tid], 1.0f);

    // load combined W2 = [W2_l | W2_r] transposed into wsT[c][k]
    for (int i = tid; i < DH * DOUT; i += 128) {
        int k = i >> 4, j = i & 15;
        wsT[j][k]      = W2l[i];
        wsT[j + 16][k] = W2r[i];
    }
    __syncthreads();   // inv visible before scaled loads below

    // load x and agg1/deg rows into packed shared layout [k][r]
    {
        float* aspf = (float*)aspv;
        float* xspf = (float*)xspv;
        for (int idx = tid; idx < 8 * DIN; idx += 128) {
            int r = idx / DIN, k = idx - r * DIN;
            size_t g = (size_t)(row0 + r) * DIN + k;
            aspf[k * 8 + r] = g_agg1[g] * inv[r];
            xspf[k * 8 + r] = x[g];
        }
    }
    __syncthreads();

    // ---- stage A: gemm1, thread = output column j ----
    const int j = tid;
    ull acc[4];
    {
        float bj = b1[j];
        ull b2p = pk(bj, bj);
#pragma unroll
        for (int p = 0; p < 4; p++) acc[p] = b2p;
    }

#pragma unroll 2
    for (int k = 0; k < DIN; k++) {
        float wl = W1l[k * DH + j];
        float wr = W1r[k * DH + j];
        ull wl2 = pk(wl, wl);
        ull wr2 = pk(wr, wr);
#pragma unroll
        for (int i = 0; i < 2; i++) {
            ulonglong2 av = aspv[k][i];
            ulonglong2 xv = xspv[k][i];
            acc[2*i]   = fma2(av.x, wl2, acc[2*i]);
            acc[2*i]   = fma2(xv.x, wr2, acc[2*i]);
            acc[2*i+1] = fma2(av.y, wl2, acc[2*i+1]);
            acc[2*i+1] = fma2(xv.y, wr2, acc[2*i+1]);
        }
    }

    // relu + stash packed h into hsT[rp][j]
#pragma unroll
    for (int p = 0; p < 4; p++) {
        float2 f = upk(acc[p]);
        hsT[p][j] = pk(fmaxf(f.x, 0.0f), fmaxf(f.y, 0.0f));
    }
    __syncthreads();

    // ---- stage B: gemm2, thread = (col c, row-pair rp) ----
    const int c  = tid & 31;
    const int rp = tid >> 5;
    const ulonglong2* hrow = (const ulonglong2*)hsT[rp];
    const float4*     wrow = (const float4*)wsT[c];

    ull acc2 = 0;
#pragma unroll 8
    for (int k4 = 0; k4 < DH / 4; k4++) {
        float4     w4  = wrow[k4];          // k .. k+3 weights for col c
        ulonglong2 h01 = hrow[2*k4];        // k, k+1 row-pair values
        ulonglong2 h23 = hrow[2*k4+1];      // k+2, k+3
        acc2 = fma2(h01.x, pk(w4.x, w4.x), acc2);
        acc2 = fma2(h01.y, pk(w4.y, w4.y), acc2);
        acc2 = fma2(h23.x, pk(w4.z, w4.z), acc2);
        acc2 = fma2(h23.y, pk(w4.w, w4.w), acc2);
    }
    float2 o2 = upk(acc2);
    g_r[(size_t)(row0 + 2*rp)     * 32 + c] = o2.x;
    g_r[(size_t)(row0 + 2*rp + 1) * 32 + c] = o2.y;
}

// ---------------- layer-2 edge aggregation of projected messages ----------------
__global__ void k_agg_p(const int* __restrict__ ei32,
                        const long long* __restrict__ ei64) {
    int gid = blockIdx.x * blockDim.x + threadIdx.x;
    if (gid >= NE * 4) return;
    int e = gid >> 2;
    int c = gid & 3;
    int src, dst;
    if (g_is64) { src = (int)ei64[e]; dst = (int)ei64[NE + e]; }
    else        { src = ei32[e];      dst = ei32[NE + e]; }

    const float4 v = ((const float4*)(g_r + (size_t)src * 32))[c];   // p = first 16
    float4* o = ((float4*)(g_agg2 + (size_t)dst * DOUT)) + c;
    asm volatile("red.global.add.v4.f32 [%0], {%1,%2,%3,%4};"
                 :: "l"(o), "f"(v.x), "f"(v.y), "f"(v.z), "f"(v.w) : "memory");
}

// ---------------- epilogue: softmax(agg2/deg + b2 + q) ----------------
__global__ void k_finalize(const float* __restrict__ b2,
                           float* __restrict__ out) {
    int row = blockIdx.x * blockDim.x + threadIdx.x;
    if (row >= NN) return;
    float inv = 1.0f / fmaxf(g_deg[row], 1.0f);

    float v[DOUT];
    float mx = -1e30f;
#pragma unroll
    for (int j = 0; j < DOUT; j++) {
        v[j] = g_agg2[(size_t)row * DOUT + j] * inv + b2[j]
             + g_r[(size_t)row * 32 + 16 + j];
        mx = fmaxf(mx, v[j]);
    }
    float s = 0.f;
#pragma unroll
    for (int j = 0; j < DOUT; j++) {
        v[j] = __expf(v[j] - mx);
        s += v[j];
    }
    float is = 1.0f / s;
#pragma unroll
    for (int j = 0; j < DOUT; j++)
        out[(size_t)row * DOUT + j] = v[j] * is;
}

// ---------------- launch ----------------
extern "C" void kernel_launch(void* const* d_in, const int* in_sizes, int n_in,
                              void* d_out, int out_size) {
    const float*     x    = (const float*)d_in[0];
    const int*       ei32 = (const int*)d_in[1];
    const long long* ei64 = (const long long*)d_in[1];
    const float*     W1l  = (const float*)d_in[2];
    const float*     b1   = (const float*)d_in[3];
    const float*     W1r  = (const float*)d_in[4];
    const float*     W2l  = (const float*)d_in[5];
    const float*     b2   = (const float*)d_in[6];
    const float*     W2r  = (const float*)d_in[7];
    float* out = (float*)d_out;

    void *agg1p, *degp, *agg2p;
    cudaGetSymbolAddress(&agg1p, g_agg1);
    cudaGetSymbolAddress(&degp,  g_deg);
    cudaGetSymbolAddress(&agg2p, g_agg2);
    cudaMemsetAsync(agg1p, 0, sizeof(float) * NN * DIN, 0);
    cudaMemsetAsync(degp,  0, sizeof(float) * NN, 0);
    cudaMemsetAsync(agg2p, 0, sizeof(float) * NN * DOUT, 0);

    k_detect<<<1, 1>>>(ei32);
    k_agg_x<<<(NE * 24 + 255) / 256, 256>>>(ei32, ei64, x);
    k_fused<<<NN / 8, 128>>>(x, W1l, b1, W1r, W2l, W2r);
    k_agg_p<<<(NE * 4 + 255) / 256, 256>>>(ei32, ei64);
    k_finalize<<<(NN + 127) / 128, 128>>>(b2, out);
}